// round 1
// baseline (speedup 1.0000x reference)
#include <cuda_runtime.h>

// Problem constants
#define G   2050            // padded grid (input)
#define N   2048            // interior grid (output / working)
#define BSZ 16              // batch
#define NITER 50
#define H2  (0.00048828125f * 0.00048828125f)   // 2^-22, exact in fp32

// Scratch: ping-pong buffer + packed premultiplied f (h2 * f_int).
// Static __device__ arrays (no allocation at runtime).
__device__ float g_w  [(size_t)BSZ * N * N];
__device__ float g_fh2[(size_t)BSZ * N * N];

// Iteration 1: stencil over `pre` (stride G, real borders), plus pack f.
//   w1[i][j] = (pre[i][j+1] + pre[i+2][j+1] + pre[i+1][j] + pre[i+1][j+2]
//               + h2*f[i+1][j+1]) * 0.25
// Also writes fh2[i][j] = h2 * f[i+1][j+1] (packed, aligned for later sweeps).
__global__ void jacobi_first(const float* __restrict__ pre,
                             const float* __restrict__ f,
                             float* __restrict__ w,
                             float* __restrict__ fh2)
{
    int x = blockIdx.x * blockDim.x + threadIdx.x;   // 0..N-1
    int y = blockIdx.y;                              // 0..N-1
    int b = blockIdx.z;                              // 0..BSZ-1
    if (x >= N) return;

    size_t base = (size_t)b * G * G;
    size_t c    = base + (size_t)(y + 1) * G + (x + 1);

    float nbr = pre[c - G] + pre[c + G] + pre[c - 1] + pre[c + 1];
    float fv  = H2 * f[c];

    size_t o = (size_t)b * N * N + (size_t)y * N + x;
    fh2[o] = fv;
    w[o]   = (nbr + fv) * 0.25f;
}

// Iterations 2..50: stencil on packed NxN grid with implicit zero boundary
// (matches jnp.pad with zeros). float4-vectorized.
__global__ void jacobi_step(const float* __restrict__ src,
                            const float* __restrict__ fh2,
                            float* __restrict__ dst)
{
    int j4 = blockIdx.x * blockDim.x + threadIdx.x;  // float4 index, 0..N/4-1
    int y  = blockIdx.y;
    int b  = blockIdx.z;
    if (j4 >= N / 4) return;

    size_t img  = (size_t)b * N * N;
    size_t row4 = (size_t)y * (N / 4) + j4;

    const float4* s4 = (const float4*)(src + img);
    const float4* f4 = (const float4*)(fh2 + img);
    float4*       d4 = (float4*)(dst + img);

    float4 zero = make_float4(0.f, 0.f, 0.f, 0.f);
    float4 top = (y > 0)     ? s4[row4 - (N / 4)] : zero;
    float4 bot = (y < N - 1) ? s4[row4 + (N / 4)] : zero;
    float4 cen = s4[row4];
    float4 fv  = f4[row4];

    int x0 = j4 * 4;
    const float* srow = src + img + (size_t)y * N;
    float uL = (x0 > 0)         ? srow[x0 - 1] : 0.f;
    float uR = (x0 + 4 < N)     ? srow[x0 + 4] : 0.f;

    float4 o;
    o.x = (top.x + bot.x + uL    + cen.y + fv.x) * 0.25f;
    o.y = (top.y + bot.y + cen.x + cen.z + fv.y) * 0.25f;
    o.z = (top.z + bot.z + cen.y + cen.w + fv.z) * 0.25f;
    o.w = (top.w + bot.w + cen.z + uR    + fv.w) * 0.25f;

    d4[row4] = o;
}

extern "C" void kernel_launch(void* const* d_in, const int* in_sizes, int n_in,
                              void* d_out, int out_size)
{
    const float* pre = (const float*)d_in[0];
    const float* f   = (const float*)d_in[1];
    float* out = (float*)d_out;

    float *w_ptr, *fh2_ptr;
    cudaGetSymbolAddress((void**)&w_ptr,   g_w);
    cudaGetSymbolAddress((void**)&fh2_ptr, g_fh2);

    // Iteration 1: pre (stride G) -> g_w, and pack h2*f_int -> g_fh2.
    {
        dim3 blk(256, 1, 1);
        dim3 grd(N / 256, N, BSZ);
        jacobi_first<<<grd, blk>>>(pre, f, w_ptr, fh2_ptr);
    }

    // Iterations 2..NITER: ping-pong g_w <-> d_out. Even iterations write
    // d_out, so iteration NITER (=50, even) lands in d_out.
    {
        dim3 blk(256, 1, 1);
        dim3 grd((N / 4) / 256, N, BSZ);   // 2 x 2048 x 16
        const float* src = w_ptr;
        for (int it = 2; it <= NITER; ++it) {
            float* dst = (it & 1) ? w_ptr : out;
            jacobi_step<<<grd, blk>>>(src, fh2_ptr, dst);
            src = dst;
        }
    }
}

// round 2
// speedup vs baseline: 1.4516x; 1.4516x over previous
#include <cuda_runtime.h>

// Problem constants
#define G    2050            // padded grid (input)
#define N    2048            // interior grid
#define BSZ  16              // batch
#define H2   (0.00048828125f * 0.00048828125f)   // 2^-22

// Temporal blocking config
#define KS   7               // fused Jacobi steps per pass
#define TX   128             // output tile x
#define TY   32              // output tile y
#define HX   8               // halo (>= KS)
#define HY   8
#define IX   (TX + 2*HX)     // 144 (in-tile width, mult of 4)
#define IY   (TY + 2*HY)     // 48  (in-tile height)
#define TPX  (IX/4)          // 36 threads in x (one float4 column each)
#define TPY  8               // threads in y
#define RPT  (IY/TPY)        // 6 rows per thread
#define NTHR (TPX*TPY)       // 288

// Scratch (static device arrays; no runtime allocation)
__device__ float g_w  [(size_t)BSZ * N * N];
__device__ float g_fh2[(size_t)BSZ * N * N];

// -------------------- iteration 1: from strided `pre`, pack h2*f --------------------
__global__ void jacobi_first(const float* __restrict__ pre,
                             const float* __restrict__ f,
                             float* __restrict__ w,
                             float* __restrict__ fh2)
{
    int x = blockIdx.x * blockDim.x + threadIdx.x;   // 0..N-1
    int y = blockIdx.y;
    int b = blockIdx.z;
    if (x >= N) return;

    size_t base = (size_t)b * G * G;
    size_t c    = base + (size_t)(y + 1) * G + (x + 1);

    float nbr = pre[c - G] + pre[c + G] + pre[c - 1] + pre[c + 1];
    float fv  = H2 * f[c];

    size_t o = (size_t)b * N * N + (size_t)y * N + x;
    fh2[o] = fv;
    w[o]   = (nbr + fv) * 0.25f;
}

// -------------------- fused 7-step Jacobi on a 144x48 smem tile --------------------
__global__ __launch_bounds__(NTHR)
void jacobi_fused(const float* __restrict__ src,
                  const float* __restrict__ fh2,
                  float* __restrict__ dst)
{
    extern __shared__ float smem[];
    float* u0 = smem;                 // IY*IX floats
    float* u1 = smem + (size_t)IY * IX;

    const int tx = threadIdx.x;       // 0..TPX-1 (float4 column)
    const int ty = threadIdx.y;       // 0..TPY-1
    const int bx = blockIdx.x, by = blockIdx.y, b = blockIdx.z;

    const int gx0 = bx * TX - HX;     // global x of in-tile ix=0
    const int gy0 = by * TY - HY;     // global y of in-tile iy=0
    const int iy0 = ty * RPT;
    const int gx  = gx0 + 4 * tx;     // global x of this thread's float4 (mult of 4)

    const float* img  = src + (size_t)b * N * N;
    const float* fimg = fh2 + (size_t)b * N * N;

    // ---- load phase: fill BOTH buffers (rim cells must be valid in both), f -> regs
    float4 fr[RPT];
    #pragma unroll
    for (int j = 0; j < RPT; ++j) {
        int iy = iy0 + j;
        int gy = gy0 + iy;
        float4 v, fv;
        if (gy >= 0 && gy < N && gx >= 0 && gx <= N - 4) {
            v  = *(const float4*)(img  + (size_t)gy * N + gx);
            fv = *(const float4*)(fimg + (size_t)gy * N + gx);
        } else {
            float t[4], ft[4];
            #pragma unroll
            for (int l = 0; l < 4; ++l) {
                int x = gx + l;
                bool in = (gy >= 0 && gy < N && x >= 0 && x < N);
                t[l]  = in ? img [(size_t)gy * N + x] : 0.f;
                ft[l] = in ? fimg[(size_t)gy * N + x] : 0.f;
            }
            v  = make_float4(t[0],  t[1],  t[2],  t[3]);
            fv = make_float4(ft[0], ft[1], ft[2], ft[3]);
        }
        ((float4*)(u0 + (size_t)iy * IX))[tx] = v;
        ((float4*)(u1 + (size_t)iy * IX))[tx] = v;
        fr[j] = fv;
    }

    // per-lane x update-mask (tile-interior AND inside global grid)
    bool mx[4];
    #pragma unroll
    for (int l = 0; l < 4; ++l) {
        int ix = 4 * tx + l;
        int x  = gx + l;
        mx[l] = (ix >= 1) && (ix <= IX - 2) && (x >= 0) && (x < N);
    }

    __syncthreads();

    // ---- KS fused steps, ping-pong u0/u1
    float* cur = u0;
    float* nxt = u1;
    #pragma unroll 1
    for (int s = 0; s < KS; ++s) {
        float4 t, m;
        if (iy0 > 0) t = ((const float4*)(cur + (size_t)(iy0 - 1) * IX))[tx];
        m = ((const float4*)(cur + (size_t)iy0 * IX))[tx];

        #pragma unroll
        for (int j = 0; j < RPT; ++j) {
            int iy = iy0 + j;
            float4 bm;
            if (iy + 1 <= IY - 1)
                bm = ((const float4*)(cur + (size_t)(iy + 1) * IX))[tx];
            if (iy >= 1 && iy <= IY - 2) {
                float lft = (tx > 0)       ? cur[(size_t)iy * IX + 4 * tx - 1] : 0.f;
                float rgt = (tx < TPX - 1) ? cur[(size_t)iy * IX + 4 * tx + 4] : 0.f;
                int  gy  = gy0 + iy;
                bool iny = (gy >= 0 && gy < N);

                float4 o;
                o.x = (t.x + bm.x + lft + m.y + fr[j].x) * 0.25f;
                o.y = (t.y + bm.y + m.x + m.z + fr[j].y) * 0.25f;
                o.z = (t.z + bm.z + m.y + m.w + fr[j].z) * 0.25f;
                o.w = (t.w + bm.w + m.z + rgt + fr[j].w) * 0.25f;
                if (!(iny && mx[0])) o.x = m.x;   // keep old value (0 outside grid)
                if (!(iny && mx[1])) o.y = m.y;
                if (!(iny && mx[2])) o.z = m.z;
                if (!(iny && mx[3])) o.w = m.w;
                ((float4*)(nxt + (size_t)iy * IX))[tx] = o;
            }
            t = m; m = bm;
        }
        __syncthreads();
        float* tmp = cur; cur = nxt; nxt = tmp;
    }

    // ---- store output region (rim >= 8): ix in [HX, HX+TX), iy in [HY, HY+TY)
    if (tx >= HX / 4 && tx < (HX + TX) / 4) {
        float* dimg = dst + (size_t)b * N * N;
        #pragma unroll
        for (int j = 0; j < RPT; ++j) {
            int iy = iy0 + j;
            if (iy >= HY && iy < HY + TY) {
                int gy = gy0 + iy;
                *(float4*)(dimg + (size_t)gy * N + gx) =
                    ((const float4*)(cur + (size_t)iy * IX))[tx];
            }
        }
    }
}

// -------------------- launch --------------------
extern "C" void kernel_launch(void* const* d_in, const int* in_sizes, int n_in,
                              void* d_out, int out_size)
{
    const float* pre = (const float*)d_in[0];
    const float* f   = (const float*)d_in[1];
    float* out = (float*)d_out;

    float *w_ptr, *fh2_ptr;
    cudaGetSymbolAddress((void**)&w_ptr,   g_w);
    cudaGetSymbolAddress((void**)&fh2_ptr, g_fh2);

    // iteration 1 + pack h2*f
    {
        dim3 blk(256, 1, 1);
        dim3 grd(N / 256, N, BSZ);
        jacobi_first<<<grd, blk>>>(pre, f, w_ptr, fh2_ptr);
    }

    // 7 fused passes x 7 steps = iterations 2..50
    {
        size_t smem_bytes = 2 * (size_t)IY * IX * sizeof(float);   // 55296
        static int attr_set = 0;
        cudaFuncSetAttribute(jacobi_fused,
                             cudaFuncAttributeMaxDynamicSharedMemorySize,
                             (int)smem_bytes);
        (void)attr_set;

        dim3 blk(TPX, TPY, 1);
        dim3 grd(N / TX, N / TY, BSZ);   // 16 x 64 x 16

        const float* s = w_ptr;
        for (int p = 0; p < 7; ++p) {
            float* d = (p & 1) ? w_ptr : out;   // pass 0,2,4,6 -> out; final (p=6) -> out
            jacobi_fused<<<grd, blk, smem_bytes>>>(s, fh2_ptr, d);
            s = d;
        }
    }
}

// round 3
// speedup vs baseline: 1.9158x; 1.3198x over previous
#include <cuda_runtime.h>

// Problem constants
#define G    2050
#define N    2048
#define BSZ  16
#define H2   (0.00048828125f * 0.00048828125f)   // 2^-22
#define KS   7               // fused Jacobi steps per pass

// Tile geometry (shared by fast + boundary kernels)
#define TX   128
#define TY   32
#define HX   8
#define HY   8
#define IX   (TX + 2*HX)     // 144
#define IY   (TY + 2*HY)     // 48
#define TPX  (IX/4)          // 36
#define TPY  8
#define RPT  (IY/TPY)        // 6
#define NTHR (TPX*TPY)       // 288

// Scratch (static device arrays; no runtime allocation)
__device__ float g_w [(size_t)BSZ * N * N];
__device__ float g_fq[(size_t)BSZ * N * N];   // h2 * f * 0.25 (packed)

// -------------------- iteration 1: from strided `pre`, pack fq --------------------
__global__ void jacobi_first(const float* __restrict__ pre,
                             const float* __restrict__ f,
                             float* __restrict__ w,
                             float* __restrict__ fq)
{
    int x = blockIdx.x * blockDim.x + threadIdx.x;
    int y = blockIdx.y;
    int b = blockIdx.z;
    if (x >= N) return;

    size_t base = (size_t)b * G * G;
    size_t c    = base + (size_t)(y + 1) * G + (x + 1);

    float nbr = pre[c - G] + pre[c + G] + pre[c - 1] + pre[c + 1];
    float fv  = H2 * f[c];

    size_t o = (size_t)b * N * N + (size_t)y * N + x;
    fq[o] = 0.25f * fv;                 // exact (power-of-two scale)
    w[o]  = (nbr + fv) * 0.25f;
}

// ============ FAST PATH: interior blocks, register-resident rows ============
__global__ __launch_bounds__(NTHR)
void jacobi_fused_int(const float* __restrict__ src,
                      const float* __restrict__ fq,
                      float* __restrict__ dst,
                      int bx0, int by0)
{
    __shared__ float topP[TPY][IX];        // published top row of each thread-row
    __shared__ float botP[TPY][IX];        // published bottom row
    __shared__ float exE[IY][TPX + 2];     // published .x of each quad (padded)
    __shared__ float ewE[IY][TPX + 2];     // published .w of each quad (padded)

    const int tx = threadIdx.x;            // 0..TPX-1
    const int ty = threadIdx.y;            // 0..TPY-1
    const int bx = blockIdx.x + bx0;
    const int by = blockIdx.y + by0;
    const int b  = blockIdx.z;

    const int gx0 = bx * TX - HX;
    const int gy0 = by * TY - HY;
    const int iy0 = ty * RPT;
    const int gx  = gx0 + 4 * tx;

    const float* img  = src + (size_t)b * N * N;
    const float* fimg = fq  + (size_t)b * N * N;

    // Load this thread's 6 rows (all strictly in-grid for interior blocks)
    float4 u[RPT], fr[RPT];
    #pragma unroll
    for (int j = 0; j < RPT; ++j) {
        int gy = gy0 + iy0 + j;
        u[j]  = *(const float4*)(img  + (size_t)gy * N + gx);
        fr[j] = *(const float4*)(fimg + (size_t)gy * N + gx);
    }

    // Zero the edge-array pad columns once (values feed only rim rings <= 6)
    {
        int tid = ty * TPX + tx;
        if (tid < IY) {
            exE[tid][0] = 0.f; exE[tid][TPX + 1] = 0.f;
            ewE[tid][0] = 0.f; ewE[tid][TPX + 1] = 0.f;
        }
    }

    #pragma unroll 1
    for (int s = 0; s < KS; ++s) {
        // ---- publish boundary info (current values)
        *(float4*)(&topP[ty][4 * tx]) = u[0];
        *(float4*)(&botP[ty][4 * tx]) = u[RPT - 1];
        #pragma unroll
        for (int j = 0; j < RPT; ++j) {
            exE[iy0 + j][tx + 1] = u[j].x;
            ewE[iy0 + j][tx + 1] = u[j].w;
        }
        __syncthreads();

        // ---- read halos
        float4 tA = make_float4(0.f, 0.f, 0.f, 0.f);
        float4 tB = make_float4(0.f, 0.f, 0.f, 0.f);
        if (ty > 0)       tA = *(const float4*)(&botP[ty - 1][4 * tx]);
        if (ty < TPY - 1) tB = *(const float4*)(&topP[ty + 1][4 * tx]);

        // ---- in-place rolling update (old u[j+1] still intact when used)
        float4 prev = tA;
        #pragma unroll
        for (int j = 0; j < RPT; ++j) {
            float4 curo = u[j];
            float4 belo = (j < RPT - 1) ? u[j + 1] : tB;
            bool doit = !((ty == 0 && j == 0) || (ty == TPY - 1 && j == RPT - 1));
            if (doit) {
                float lf = ewE[iy0 + j][tx];
                float rg = exE[iy0 + j][tx + 2];
                float4 o;
                o.x = fmaf(((prev.x + belo.x) + lf)     + curo.y, 0.25f, fr[j].x);
                o.y = fmaf(((prev.y + belo.y) + curo.x) + curo.z, 0.25f, fr[j].y);
                o.z = fmaf(((prev.z + belo.z) + curo.y) + curo.w, 0.25f, fr[j].z);
                o.w = fmaf(((prev.w + belo.w) + curo.z) + rg,     0.25f, fr[j].w);
                u[j] = o;
            }
            prev = curo;
        }
        if (s < KS - 1) __syncthreads();   // protect published data until next publish
    }

    // ---- store: output region rings >= 8; results are in registers, no sync needed
    if (tx >= HX / 4 && tx < (HX + TX) / 4) {
        float* dimg = dst + (size_t)b * N * N;
        #pragma unroll
        for (int j = 0; j < RPT; ++j) {
            int iy = iy0 + j;
            if (iy >= HY && iy < HY + TY) {
                *(float4*)(dimg + (size_t)(gy0 + iy) * N + gx) = u[j];
            }
        }
    }
}

// ============ BOUNDARY PATH: masked smem ping-pong (round-2 kernel) ============
__global__ __launch_bounds__(NTHR)
void jacobi_fused_bnd(const float* __restrict__ src,
                      const float* __restrict__ fq,
                      float* __restrict__ dst,
                      int bx0, int by0)
{
    extern __shared__ float smem[];
    float* u0 = smem;
    float* u1 = smem + (size_t)IY * IX;

    const int tx = threadIdx.x;
    const int ty = threadIdx.y;
    const int bx = blockIdx.x + bx0, by = blockIdx.y + by0, b = blockIdx.z;

    const int gx0 = bx * TX - HX;
    const int gy0 = by * TY - HY;
    const int iy0 = ty * RPT;
    const int gx  = gx0 + 4 * tx;

    const float* img  = src + (size_t)b * N * N;
    const float* fimg = fq  + (size_t)b * N * N;

    float4 fr[RPT];
    #pragma unroll
    for (int j = 0; j < RPT; ++j) {
        int iy = iy0 + j;
        int gy = gy0 + iy;
        float4 v, fv;
        if (gy >= 0 && gy < N && gx >= 0 && gx <= N - 4) {
            v  = *(const float4*)(img  + (size_t)gy * N + gx);
            fv = *(const float4*)(fimg + (size_t)gy * N + gx);
        } else {
            float t[4], ft[4];
            #pragma unroll
            for (int l = 0; l < 4; ++l) {
                int x = gx + l;
                bool in = (gy >= 0 && gy < N && x >= 0 && x < N);
                t[l]  = in ? img [(size_t)gy * N + x] : 0.f;
                ft[l] = in ? fimg[(size_t)gy * N + x] : 0.f;
            }
            v  = make_float4(t[0],  t[1],  t[2],  t[3]);
            fv = make_float4(ft[0], ft[1], ft[2], ft[3]);
        }
        ((float4*)(u0 + (size_t)iy * IX))[tx] = v;
        ((float4*)(u1 + (size_t)iy * IX))[tx] = v;
        fr[j] = fv;
    }

    bool mx[4];
    #pragma unroll
    for (int l = 0; l < 4; ++l) {
        int ix = 4 * tx + l;
        int x  = gx + l;
        mx[l] = (ix >= 1) && (ix <= IX - 2) && (x >= 0) && (x < N);
    }

    __syncthreads();

    float* cur = u0;
    float* nxt = u1;
    #pragma unroll 1
    for (int s = 0; s < KS; ++s) {
        float4 t, m;
        if (iy0 > 0) t = ((const float4*)(cur + (size_t)(iy0 - 1) * IX))[tx];
        m = ((const float4*)(cur + (size_t)iy0 * IX))[tx];

        #pragma unroll
        for (int j = 0; j < RPT; ++j) {
            int iy = iy0 + j;
            float4 bm;
            if (iy + 1 <= IY - 1)
                bm = ((const float4*)(cur + (size_t)(iy + 1) * IX))[tx];
            if (iy >= 1 && iy <= IY - 2) {
                float lft = (tx > 0)       ? cur[(size_t)iy * IX + 4 * tx - 1] : 0.f;
                float rgt = (tx < TPX - 1) ? cur[(size_t)iy * IX + 4 * tx + 4] : 0.f;
                int  gy  = gy0 + iy;
                bool iny = (gy >= 0 && gy < N);

                float4 o;
                o.x = fmaf(((t.x + bm.x) + lft)  + m.y, 0.25f, fr[j].x);
                o.y = fmaf(((t.y + bm.y) + m.x)  + m.z, 0.25f, fr[j].y);
                o.z = fmaf(((t.z + bm.z) + m.y)  + m.w, 0.25f, fr[j].z);
                o.w = fmaf(((t.w + bm.w) + m.z)  + rgt, 0.25f, fr[j].w);
                if (!(iny && mx[0])) o.x = m.x;
                if (!(iny && mx[1])) o.y = m.y;
                if (!(iny && mx[2])) o.z = m.z;
                if (!(iny && mx[3])) o.w = m.w;
                ((float4*)(nxt + (size_t)iy * IX))[tx] = o;
            }
            t = m; m = bm;
        }
        __syncthreads();
        float* tmp = cur; cur = nxt; nxt = tmp;
    }

    if (tx >= HX / 4 && tx < (HX + TX) / 4) {
        float* dimg = dst + (size_t)b * N * N;
        #pragma unroll
        for (int j = 0; j < RPT; ++j) {
            int iy = iy0 + j;
            if (iy >= HY && iy < HY + TY) {
                int gy = gy0 + iy;
                *(float4*)(dimg + (size_t)gy * N + gx) =
                    ((const float4*)(cur + (size_t)iy * IX))[tx];
            }
        }
    }
}

// -------------------- launch --------------------
extern "C" void kernel_launch(void* const* d_in, const int* in_sizes, int n_in,
                              void* d_out, int out_size)
{
    const float* pre = (const float*)d_in[0];
    const float* f   = (const float*)d_in[1];
    float* out = (float*)d_out;

    float *w_ptr, *fq_ptr;
    cudaGetSymbolAddress((void**)&w_ptr,  g_w);
    cudaGetSymbolAddress((void**)&fq_ptr, g_fq);

    // iteration 1 + pack fq
    {
        dim3 blk(256, 1, 1);
        dim3 grd(N / 256, N, BSZ);
        jacobi_first<<<grd, blk>>>(pre, f, w_ptr, fq_ptr);
    }

    // 7 fused passes x 7 steps = iterations 2..50
    {
        size_t smem_bnd = 2 * (size_t)IY * IX * sizeof(float);   // 55296
        cudaFuncSetAttribute(jacobi_fused_bnd,
                             cudaFuncAttributeMaxDynamicSharedMemorySize,
                             (int)smem_bnd);

        dim3 blk(TPX, TPY, 1);
        const int NBX = N / TX;   // 16
        const int NBY = N / TY;   // 64

        const float* s = w_ptr;
        for (int p = 0; p < 7; ++p) {
            float* d = (p & 1) ? w_ptr : out;   // final pass (p=6) -> out

            // interior (fast, register-resident)
            jacobi_fused_int<<<dim3(NBX - 2, NBY - 2, BSZ), blk>>>(s, fq_ptr, d, 1, 1);
            // boundary strips (masked)
            jacobi_fused_bnd<<<dim3(NBX, 1, BSZ), blk, smem_bnd>>>(s, fq_ptr, d, 0, 0);
            jacobi_fused_bnd<<<dim3(NBX, 1, BSZ), blk, smem_bnd>>>(s, fq_ptr, d, 0, NBY - 1);
            jacobi_fused_bnd<<<dim3(1, NBY - 2, BSZ), blk, smem_bnd>>>(s, fq_ptr, d, 0, 1);
            jacobi_fused_bnd<<<dim3(1, NBY - 2, BSZ), blk, smem_bnd>>>(s, fq_ptr, d, NBX - 1, 1);

            s = d;
        }
    }
}

// round 4
// speedup vs baseline: 2.4433x; 1.2753x over previous
#include <cuda_runtime.h>

// Problem constants
#define G    2050
#define N    2048
#define BSZ  16
#define H2   (0.00048828125f * 0.00048828125f)   // 2^-22
#define KS   7               // fused Jacobi steps per pass

// Tile geometry
#define TX   128
#define TY   32
#define HX   8
#define HY   8
#define IX   (TX + 2*HX)     // 144
#define IY   (TY + 2*HY)     // 48
#define TPX  (IX/4)          // 36
#define TPY  8
#define RPT  (IY/TPY)        // 6
#define NTHR (TPX*TPY)       // 288
#define NBX  (N/TX)          // 16
#define NBY  (N/TY)          // 64

// Scratch (static device arrays; no runtime allocation)
__device__ float g_w [(size_t)BSZ * N * N];
__device__ float g_fq[(size_t)BSZ * N * N];   // h2 * f * 0.25 (packed)

// -------------------- iteration 1: from strided `pre`, pack fq --------------------
__global__ void jacobi_first(const float* __restrict__ pre,
                             const float* __restrict__ f,
                             float* __restrict__ w,
                             float* __restrict__ fq)
{
    int x = blockIdx.x * blockDim.x + threadIdx.x;
    int y = blockIdx.y;
    int b = blockIdx.z;
    if (x >= N) return;

    size_t base = (size_t)b * G * G;
    size_t c    = base + (size_t)(y + 1) * G + (x + 1);

    float nbr = pre[c - G] + pre[c + G] + pre[c - 1] + pre[c + 1];
    float fv  = H2 * f[c];

    size_t o = (size_t)b * N * N + (size_t)y * N + x;
    fq[o] = 0.25f * fv;                 // exact (power-of-two scale)
    w[o]  = (nbr + fv) * 0.25f;
}

// -------------------- fused KS-step core (register-resident rows) --------------------
// Double-buffered publish arrays -> ONE barrier per step.
template<bool MASKED>
__device__ __forceinline__ void steps_loop(
    float4 (&u)[RPT], const float4 (&fr)[RPT],
    float (&topP)[2][TPY][IX], float (&botP)[2][TPY][IX],
    float (&exE)[2][IY][TPX + 2], float (&ewE)[2][IY][TPX + 2],
    int tx, int ty, int iy0, const bool (&mx)[4], const bool (&my)[RPT])
{
    #pragma unroll 1
    for (int s = 0; s < KS; ++s) {
        const int p = s & 1;

        // publish boundary info (current values)
        *(float4*)(&topP[p][ty][4 * tx]) = u[0];
        *(float4*)(&botP[p][ty][4 * tx]) = u[RPT - 1];
        #pragma unroll
        for (int j = 0; j < RPT; ++j) {
            exE[p][iy0 + j][tx + 1] = u[j].x;
            ewE[p][iy0 + j][tx + 1] = u[j].w;
        }
        __syncthreads();

        float4 tA = make_float4(0.f, 0.f, 0.f, 0.f);
        float4 tB = make_float4(0.f, 0.f, 0.f, 0.f);
        if (ty > 0)       tA = *(const float4*)(&botP[p][ty - 1][4 * tx]);
        if (ty < TPY - 1) tB = *(const float4*)(&topP[p][ty + 1][4 * tx]);

        // in-place rolling update (old u[j+1] intact when used)
        float4 prev = tA;
        #pragma unroll
        for (int j = 0; j < RPT; ++j) {
            float4 curo = u[j];
            float4 belo = (j < RPT - 1) ? u[j + 1] : tB;
            bool doit = !((ty == 0 && j == 0) || (ty == TPY - 1 && j == RPT - 1));
            if (doit) {
                float lf = ewE[p][iy0 + j][tx];
                float rg = exE[p][iy0 + j][tx + 2];
                float4 o;
                o.x = fmaf(((prev.x + belo.x) + lf)     + curo.y, 0.25f, fr[j].x);
                o.y = fmaf(((prev.y + belo.y) + curo.x) + curo.z, 0.25f, fr[j].y);
                o.z = fmaf(((prev.z + belo.z) + curo.y) + curo.w, 0.25f, fr[j].z);
                o.w = fmaf(((prev.w + belo.w) + curo.z) + rg,     0.25f, fr[j].w);
                if (MASKED) {
                    // out-of-grid cells keep their value (0) => matches jnp.pad
                    if (!(my[j] && mx[0])) o.x = curo.x;
                    if (!(my[j] && mx[1])) o.y = curo.y;
                    if (!(my[j] && mx[2])) o.z = curo.z;
                    if (!(my[j] && mx[3])) o.w = curo.w;
                }
                u[j] = o;
            }
            prev = curo;
        }
    }
}

// -------------------- unified fused kernel: one launch per pass --------------------
__global__ __launch_bounds__(NTHR)
void jacobi_fused(const float* __restrict__ src,
                  const float* __restrict__ fq,
                  float* __restrict__ dst)
{
    __shared__ float topP[2][TPY][IX];
    __shared__ float botP[2][TPY][IX];
    __shared__ float exE [2][IY][TPX + 2];
    __shared__ float ewE [2][IY][TPX + 2];

    const int tx = threadIdx.x;           // 0..TPX-1 (one float4 column)
    const int ty = threadIdx.y;           // 0..TPY-1
    const int bx = blockIdx.x, by = blockIdx.y, b = blockIdx.z;

    const int gx0 = bx * TX - HX;
    const int gy0 = by * TY - HY;
    const int iy0 = ty * RPT;
    const int gx  = gx0 + 4 * tx;

    const bool edge = (bx == 0) | (bx == NBX - 1) | (by == 0) | (by == NBY - 1);

    const float* img  = src + (size_t)b * N * N;
    const float* fimg = fq  + (size_t)b * N * N;

    // ---- load rows + masks
    float4 u[RPT], fr[RPT];
    bool mx[4], my[RPT];
    #pragma unroll
    for (int l = 0; l < 4; ++l) {
        int x = gx + l;
        mx[l] = (x >= 0) && (x < N);
    }

    if (!edge) {
        #pragma unroll
        for (int j = 0; j < RPT; ++j) {
            int gy = gy0 + iy0 + j;
            my[j] = true;
            u[j]  = *(const float4*)(img  + (size_t)gy * N + gx);
            fr[j] = *(const float4*)(fimg + (size_t)gy * N + gx);
        }
    } else {
        #pragma unroll
        for (int j = 0; j < RPT; ++j) {
            int gy = gy0 + iy0 + j;
            my[j] = (gy >= 0) && (gy < N);
            float4 v, fv;
            if (my[j] && gx >= 0 && gx <= N - 4) {
                v  = *(const float4*)(img  + (size_t)gy * N + gx);
                fv = *(const float4*)(fimg + (size_t)gy * N + gx);
            } else {
                float t[4], ft[4];
                #pragma unroll
                for (int l = 0; l < 4; ++l) {
                    bool in = my[j] && mx[l];
                    t[l]  = in ? img [(size_t)gy * N + (gx + l)] : 0.f;
                    ft[l] = in ? fimg[(size_t)gy * N + (gx + l)] : 0.f;
                }
                v  = make_float4(t[0],  t[1],  t[2],  t[3]);
                fv = make_float4(ft[0], ft[1], ft[2], ft[3]);
            }
            u[j]  = v;
            fr[j] = fv;
        }
    }

    // zero pad columns of edge arrays (both buffers), once
    {
        int tid = ty * TPX + tx;
        if (tid < IY) {
            exE[0][tid][0] = 0.f; exE[0][tid][TPX + 1] = 0.f;
            ewE[0][tid][0] = 0.f; ewE[0][tid][TPX + 1] = 0.f;
            exE[1][tid][0] = 0.f; exE[1][tid][TPX + 1] = 0.f;
            ewE[1][tid][0] = 0.f; ewE[1][tid][TPX + 1] = 0.f;
        }
    }
    __syncthreads();

    if (!edge) steps_loop<false>(u, fr, topP, botP, exE, ewE, tx, ty, iy0, mx, my);
    else       steps_loop<true >(u, fr, topP, botP, exE, ewE, tx, ty, iy0, mx, my);

    // ---- store output region (rings >= 8); results live in registers
    if (tx >= HX / 4 && tx < (HX + TX) / 4) {
        float* dimg = dst + (size_t)b * N * N;
        #pragma unroll
        for (int j = 0; j < RPT; ++j) {
            int iy = iy0 + j;
            if (iy >= HY && iy < HY + TY) {
                *(float4*)(dimg + (size_t)(gy0 + iy) * N + gx) = u[j];
            }
        }
    }
}

// -------------------- launch --------------------
extern "C" void kernel_launch(void* const* d_in, const int* in_sizes, int n_in,
                              void* d_out, int out_size)
{
    const float* pre = (const float*)d_in[0];
    const float* f   = (const float*)d_in[1];
    float* out = (float*)d_out;

    float *w_ptr, *fq_ptr;
    cudaGetSymbolAddress((void**)&w_ptr,  g_w);
    cudaGetSymbolAddress((void**)&fq_ptr, g_fq);

    // iteration 1 + pack fq
    {
        dim3 blk(256, 1, 1);
        dim3 grd(N / 256, N, BSZ);
        jacobi_first<<<grd, blk>>>(pre, f, w_ptr, fq_ptr);
    }

    // 7 fused passes x 7 steps = iterations 2..50 (single launch per pass)
    {
        dim3 blk(TPX, TPY, 1);
        dim3 grd(NBX, NBY, BSZ);   // 16 x 64 x 16

        const float* s = w_ptr;
        for (int p = 0; p < 7; ++p) {
            float* d = (p & 1) ? w_ptr : out;   // final pass (p=6) -> out
            jacobi_fused<<<grd, blk>>>(s, fq_ptr, d);
            s = d;
        }
    }
}

// round 5
// speedup vs baseline: 2.7327x; 1.1185x over previous
#include <cuda_runtime.h>

// Problem constants
#define G    2050
#define N    2048
#define BSZ  16
#define H2   (0.00048828125f * 0.00048828125f)   // 2^-22
#define KS   7               // fused Jacobi steps per pass

// Tile geometry: one warp spans full tile width
#define HX   8
#define HY   8
#define IX   128             // 32 lanes x float4
#define TX   (IX - 2*HX)     // 112 output cols
#define TY   32
#define IY   (TY + 2*HY)     // 48
#define TPY  8
#define RPT  (IY/TPY)        // 6
#define NTHR (32*TPY)        // 256
#define NBX  ((N + TX - 1)/TX)   // 19
#define NBY  (N/TY)              // 64

// Scratch (static device arrays; no runtime allocation)
__device__ float g_w [(size_t)BSZ * N * N];
__device__ float g_fq[(size_t)BSZ * N * N];   // h2 * f * 0.25 (packed)

// -------------------- iteration 1: from strided `pre`, pack fq --------------------
__global__ void jacobi_first(const float* __restrict__ pre,
                             const float* __restrict__ f,
                             float* __restrict__ w,
                             float* __restrict__ fq)
{
    int x = blockIdx.x * blockDim.x + threadIdx.x;
    int y = blockIdx.y;
    int b = blockIdx.z;
    if (x >= N) return;

    size_t base = (size_t)b * G * G;
    size_t c    = base + (size_t)(y + 1) * G + (x + 1);

    float nbr = pre[c - G] + pre[c + G] + pre[c - 1] + pre[c + 1];
    float fv  = H2 * f[c];

    size_t o = (size_t)b * N * N + (size_t)y * N + x;
    fq[o] = 0.25f * fv;                 // exact (power-of-two scale)
    w[o]  = (nbr + fv) * 0.25f;
}

// -------------------- fused KS-step core --------------------
// x-neighbor exchange via warp shuffles; y-exchange via double-buffered smem
// rows with ONE barrier per step.
template<bool MASKED>
__device__ __forceinline__ void steps_loop(
    float4 (&u)[RPT], const float4 (&fr)[RPT],
    float (&topP)[2][TPY][IX], float (&botP)[2][TPY][IX],
    int lane, int ty, const bool (&mx)[4], const bool (&my)[RPT])
{
    #pragma unroll 1
    for (int s = 0; s < KS; ++s) {
        const int p = s & 1;

        // publish this thread's top & bottom rows
        *(float4*)(&topP[p][ty][4 * lane]) = u[0];
        *(float4*)(&botP[p][ty][4 * lane]) = u[RPT - 1];
        __syncthreads();

        float4 tA = make_float4(0.f, 0.f, 0.f, 0.f);
        float4 tB = make_float4(0.f, 0.f, 0.f, 0.f);
        if (ty > 0)       tA = *(const float4*)(&botP[p][ty - 1][4 * lane]);
        if (ty < TPY - 1) tB = *(const float4*)(&topP[p][ty + 1][4 * lane]);

        // in-place rolling update (old u[j+1] intact when used)
        float4 prev = tA;
        #pragma unroll
        for (int j = 0; j < RPT; ++j) {
            float4 curo = u[j];
            float4 belo = (j < RPT - 1) ? u[j + 1] : tB;
            // x-neighbors across lanes (lane 0 / lane 31 get self values ->
            // tile ring 0 garbage, tolerated: front reaches ring <= 6 after
            // 7 steps, outputs sit at ring >= 8)
            float lf = __shfl_up_sync(0xffffffffu, curo.w, 1);
            float rg = __shfl_down_sync(0xffffffffu, curo.x, 1);

            bool doit = !((ty == 0 && j == 0) || (ty == TPY - 1 && j == RPT - 1));
            if (doit) {
                float4 o;
                o.x = fmaf((prev.x + belo.x) + (lf     + curo.y), 0.25f, fr[j].x);
                o.y = fmaf((prev.y + belo.y) + (curo.x + curo.z), 0.25f, fr[j].y);
                o.z = fmaf((prev.z + belo.z) + (curo.y + curo.w), 0.25f, fr[j].z);
                o.w = fmaf((prev.w + belo.w) + (curo.z + rg),     0.25f, fr[j].w);
                if (MASKED) {
                    // out-of-grid cells keep their value (0) => matches jnp.pad
                    if (!(my[j] && mx[0])) o.x = curo.x;
                    if (!(my[j] && mx[1])) o.y = curo.y;
                    if (!(my[j] && mx[2])) o.z = curo.z;
                    if (!(my[j] && mx[3])) o.w = curo.w;
                }
                u[j] = o;
            }
            prev = curo;
        }
    }
}

// -------------------- unified fused kernel: one launch per pass --------------------
__global__ __launch_bounds__(NTHR)
void jacobi_fused(const float* __restrict__ src,
                  const float* __restrict__ fq,
                  float* __restrict__ dst)
{
    __shared__ float topP[2][TPY][IX];
    __shared__ float botP[2][TPY][IX];

    const int lane = threadIdx.x;          // 0..31, one float4 column each
    const int ty   = threadIdx.y;          // 0..TPY-1
    const int bx = blockIdx.x, by = blockIdx.y, b = blockIdx.z;

    const int gx0 = bx * TX - HX;
    const int gy0 = by * TY - HY;
    const int iy0 = ty * RPT;
    const int gx  = gx0 + 4 * lane;

    const bool edge = (bx == 0) | (bx == NBX - 1) | (by == 0) | (by == NBY - 1);

    const float* img  = src + (size_t)b * N * N;
    const float* fimg = fq  + (size_t)b * N * N;

    // ---- load rows + masks
    float4 u[RPT], fr[RPT];
    bool mx[4], my[RPT];
    #pragma unroll
    for (int l = 0; l < 4; ++l) {
        int x = gx + l;
        mx[l] = (x >= 0) && (x < N);
    }

    if (!edge) {
        #pragma unroll
        for (int j = 0; j < RPT; ++j) {
            int gy = gy0 + iy0 + j;
            my[j] = true;
            u[j]  = *(const float4*)(img  + (size_t)gy * N + gx);
            fr[j] = *(const float4*)(fimg + (size_t)gy * N + gx);
        }
    } else {
        #pragma unroll
        for (int j = 0; j < RPT; ++j) {
            int gy = gy0 + iy0 + j;
            my[j] = (gy >= 0) && (gy < N);
            float4 v, fv;
            if (my[j] && gx >= 0 && gx <= N - 4) {
                v  = *(const float4*)(img  + (size_t)gy * N + gx);
                fv = *(const float4*)(fimg + (size_t)gy * N + gx);
            } else {
                float t[4], ft[4];
                #pragma unroll
                for (int l = 0; l < 4; ++l) {
                    bool in = my[j] && mx[l];
                    t[l]  = in ? img [(size_t)gy * N + (gx + l)] : 0.f;
                    ft[l] = in ? fimg[(size_t)gy * N + (gx + l)] : 0.f;
                }
                v  = make_float4(t[0],  t[1],  t[2],  t[3]);
                fv = make_float4(ft[0], ft[1], ft[2], ft[3]);
            }
            u[j]  = v;
            fr[j] = fv;
        }
    }

    if (!edge) steps_loop<false>(u, fr, topP, botP, lane, ty, mx, my);
    else       steps_loop<true >(u, fr, topP, botP, lane, ty, mx, my);

    // ---- store output region: ix in [HX, HX+TX) -> lanes 2..29, iy in [HY, HY+TY)
    // For the last x-block, lanes whose float4 crosses x=N are fully out of
    // grid at float4 granularity (offsets are multiples of 4), so a whole-
    // vector in-grid test suffices.
    if (lane >= HX / 4 && lane < (HX + TX) / 4 && gx >= 0 && gx <= N - 4) {
        float* dimg = dst + (size_t)b * N * N;
        #pragma unroll
        for (int j = 0; j < RPT; ++j) {
            int iy = iy0 + j;
            if (iy >= HY && iy < HY + TY) {
                *(float4*)(dimg + (size_t)(gy0 + iy) * N + gx) = u[j];
            }
        }
    }
}

// -------------------- launch --------------------
extern "C" void kernel_launch(void* const* d_in, const int* in_sizes, int n_in,
                              void* d_out, int out_size)
{
    const float* pre = (const float*)d_in[0];
    const float* f   = (const float*)d_in[1];
    float* out = (float*)d_out;

    float *w_ptr, *fq_ptr;
    cudaGetSymbolAddress((void**)&w_ptr,  g_w);
    cudaGetSymbolAddress((void**)&fq_ptr, g_fq);

    // iteration 1 + pack fq
    {
        dim3 blk(256, 1, 1);
        dim3 grd(N / 256, N, BSZ);
        jacobi_first<<<grd, blk>>>(pre, f, w_ptr, fq_ptr);
    }

    // 7 fused passes x 7 steps = iterations 2..50 (single launch per pass)
    {
        dim3 blk(32, TPY, 1);
        dim3 grd(NBX, NBY, BSZ);   // 19 x 64 x 16

        const float* s = w_ptr;
        for (int p = 0; p < 7; ++p) {
            float* d = (p & 1) ? w_ptr : out;   // final pass (p=6) -> out
            jacobi_fused<<<grd, blk>>>(s, fq_ptr, d);
            s = d;
        }
    }
}

// round 6
// speedup vs baseline: 2.8661x; 1.0488x over previous
#include <cuda_runtime.h>
#include <cstdint>

// Problem constants
#define G    2050
#define N    2048
#define BSZ  16
#define H2   (0.00048828125f * 0.00048828125f)   // 2^-22
#define KS   7               // fused Jacobi steps per pass

// Tile geometry: one warp spans full tile width
#define HX   8
#define HY   8
#define IX   128             // 32 lanes x float4
#define TX   (IX - 2*HX)     // 112 output cols
#define TY   32
#define IY   (TY + 2*HY)     // 48
#define TPY  8
#define RPT  (IY/TPY)        // 6
#define NTHR (32*TPY)        // 256
#define NBX  ((N + TX - 1)/TX)   // 19
#define NBY  (N/TY)              // 64

// Scratch (static device arrays; no runtime allocation)
__device__ float g_w [(size_t)BSZ * N * N];
__device__ float g_fq[(size_t)BSZ * N * N];   // h2 * f * 0.25 (packed)

// ---------------- packed f32x2 helpers (Blackwell) ----------------
__device__ __forceinline__ uint64_t pk2(float lo, float hi) {
    uint64_t r; asm("mov.b64 %0, {%1, %2};" : "=l"(r) : "f"(lo), "f"(hi)); return r;
}
__device__ __forceinline__ uint64_t add2(uint64_t a, uint64_t b) {
    uint64_t r; asm("add.rn.f32x2 %0, %1, %2;" : "=l"(r) : "l"(a), "l"(b)); return r;
}
__device__ __forceinline__ uint64_t fma2(uint64_t a, uint64_t b, uint64_t c) {
    uint64_t r; asm("fma.rn.f32x2 %0, %1, %2, %3;" : "=l"(r) : "l"(a), "l"(b), "l"(c)); return r;
}
__device__ __forceinline__ void upk2(uint64_t v, float& lo, float& hi) {
    asm("mov.b64 {%0, %1}, %2;" : "=f"(lo), "=f"(hi) : "l"(v));
}

// -------------------- iteration 1: from strided `pre`, pack fq --------------------
__global__ void jacobi_first(const float* __restrict__ pre,
                             const float* __restrict__ f,
                             float* __restrict__ w,
                             float* __restrict__ fq)
{
    int x = blockIdx.x * blockDim.x + threadIdx.x;
    int y = blockIdx.y;
    int b = blockIdx.z;
    if (x >= N) return;

    size_t base = (size_t)b * G * G;
    size_t c    = base + (size_t)(y + 1) * G + (x + 1);

    float nbr = pre[c - G] + pre[c + G] + pre[c - 1] + pre[c + 1];
    float fv  = H2 * f[c];

    size_t o = (size_t)b * N * N + (size_t)y * N + x;
    fq[o] = 0.25f * fv;                 // exact (power-of-two scale)
    w[o]  = (nbr + fv) * 0.25f;
}

// -------------------- fused KS-step core --------------------
// x-neighbor exchange via warp shuffles; y-exchange via double-buffered smem
// rows with ONE barrier per step; update math in packed f32x2.
template<bool MASKED>
__device__ __forceinline__ void steps_loop(
    float4 (&u)[RPT], const float4 (&fr)[RPT],
    float (&topP)[2][TPY][IX], float (&botP)[2][TPY][IX],
    int lane, int ty, const bool (&mx)[4], const bool (&my)[RPT])
{
    const uint64_t Q2 = pk2(0.25f, 0.25f);

    #pragma unroll 1
    for (int s = 0; s < KS; ++s) {
        const int p = s & 1;

        // publish this thread's top & bottom rows
        *(float4*)(&topP[p][ty][4 * lane]) = u[0];
        *(float4*)(&botP[p][ty][4 * lane]) = u[RPT - 1];
        __syncthreads();

        float4 tA = make_float4(0.f, 0.f, 0.f, 0.f);
        float4 tB = make_float4(0.f, 0.f, 0.f, 0.f);
        if (ty > 0)       tA = *(const float4*)(&botP[p][ty - 1][4 * lane]);
        if (ty < TPY - 1) tB = *(const float4*)(&topP[p][ty + 1][4 * lane]);

        // in-place rolling update (old u[j+1] intact when used)
        float4 prev = tA;
        #pragma unroll
        for (int j = 0; j < RPT; ++j) {
            float4 curo = u[j];
            float4 belo = (j < RPT - 1) ? u[j + 1] : tB;
            // x-neighbors across lanes (lane 0 / 31 self-values -> ring 0,
            // tolerated: front reaches ring <= 6 after 7 steps, outputs >= 8)
            float lf = __shfl_up_sync(0xffffffffu, curo.w, 1);
            float rg = __shfl_down_sync(0xffffffffu, curo.x, 1);

            bool doit = !((ty == 0 && j == 0) || (ty == TPY - 1 && j == RPT - 1));
            if (doit) {
                // o.x = ((prev.x+belo.x) + (lf    +curo.y)) * .25 + fr.x
                // o.y = ((prev.y+belo.y) + (curo.x+curo.z)) * .25 + fr.y
                // o.z = ((prev.z+belo.z) + (curo.y+curo.w)) * .25 + fr.z
                // o.w = ((prev.w+belo.w) + (curo.z+rg    )) * .25 + fr.w
                uint64_t P   = pk2(curo.y, curo.z);           // shared pair
                uint64_t t01 = add2(pk2(lf, curo.x), P);
                uint64_t t23 = add2(P, pk2(curo.w, rg));
                uint64_t s01 = add2(pk2(prev.x, prev.y), pk2(belo.x, belo.y));
                uint64_t s23 = add2(pk2(prev.z, prev.w), pk2(belo.z, belo.w));
                uint64_t o01 = fma2(add2(s01, t01), Q2, pk2(fr[j].x, fr[j].y));
                uint64_t o23 = fma2(add2(s23, t23), Q2, pk2(fr[j].z, fr[j].w));
                float4 o;
                upk2(o01, o.x, o.y);
                upk2(o23, o.z, o.w);
                if (MASKED) {
                    // out-of-grid cells keep their value (0) => matches jnp.pad
                    if (!(my[j] && mx[0])) o.x = curo.x;
                    if (!(my[j] && mx[1])) o.y = curo.y;
                    if (!(my[j] && mx[2])) o.z = curo.z;
                    if (!(my[j] && mx[3])) o.w = curo.w;
                }
                u[j] = o;
            }
            prev = curo;
        }
    }
}

// -------------------- unified fused kernel: one launch per pass --------------------
__global__ __launch_bounds__(NTHR, 3)
void jacobi_fused(const float* __restrict__ src,
                  const float* __restrict__ fq,
                  float* __restrict__ dst)
{
    __shared__ float topP[2][TPY][IX];
    __shared__ float botP[2][TPY][IX];

    const int lane = threadIdx.x;          // 0..31, one float4 column each
    const int ty   = threadIdx.y;          // 0..TPY-1
    const int bx = blockIdx.x, by = blockIdx.y, b = blockIdx.z;

    const int gx0 = bx * TX - HX;
    const int gy0 = by * TY - HY;
    const int iy0 = ty * RPT;
    const int gx  = gx0 + 4 * lane;

    const bool edge = (bx == 0) | (bx == NBX - 1) | (by == 0) | (by == NBY - 1);

    const float* img  = src + (size_t)b * N * N;
    const float* fimg = fq  + (size_t)b * N * N;

    // ---- load rows + masks
    float4 u[RPT], fr[RPT];
    bool mx[4], my[RPT];
    #pragma unroll
    for (int l = 0; l < 4; ++l) {
        int x = gx + l;
        mx[l] = (x >= 0) && (x < N);
    }

    if (!edge) {
        #pragma unroll
        for (int j = 0; j < RPT; ++j) {
            int gy = gy0 + iy0 + j;
            my[j] = true;
            u[j]  = *(const float4*)(img  + (size_t)gy * N + gx);
            fr[j] = *(const float4*)(fimg + (size_t)gy * N + gx);
        }
    } else {
        #pragma unroll
        for (int j = 0; j < RPT; ++j) {
            int gy = gy0 + iy0 + j;
            my[j] = (gy >= 0) && (gy < N);
            float4 v, fv;
            if (my[j] && gx >= 0 && gx <= N - 4) {
                v  = *(const float4*)(img  + (size_t)gy * N + gx);
                fv = *(const float4*)(fimg + (size_t)gy * N + gx);
            } else {
                float t[4], ft[4];
                #pragma unroll
                for (int l = 0; l < 4; ++l) {
                    bool in = my[j] && mx[l];
                    t[l]  = in ? img [(size_t)gy * N + (gx + l)] : 0.f;
                    ft[l] = in ? fimg[(size_t)gy * N + (gx + l)] : 0.f;
                }
                v  = make_float4(t[0],  t[1],  t[2],  t[3]);
                fv = make_float4(ft[0], ft[1], ft[2], ft[3]);
            }
            u[j]  = v;
            fr[j] = fv;
        }
    }

    if (!edge) steps_loop<false>(u, fr, topP, botP, lane, ty, mx, my);
    else       steps_loop<true >(u, fr, topP, botP, lane, ty, mx, my);

    // ---- store output region: ix in [HX, HX+TX), iy in [HY, HY+TY).
    // Last x-block: out-of-grid float4s are entirely out (offsets mult of 4),
    // so a whole-vector test suffices.
    if (lane >= HX / 4 && lane < (HX + TX) / 4 && gx >= 0 && gx <= N - 4) {
        float* dimg = dst + (size_t)b * N * N;
        #pragma unroll
        for (int j = 0; j < RPT; ++j) {
            int iy = iy0 + j;
            if (iy >= HY && iy < HY + TY) {
                *(float4*)(dimg + (size_t)(gy0 + iy) * N + gx) = u[j];
            }
        }
    }
}

// -------------------- launch --------------------
extern "C" void kernel_launch(void* const* d_in, const int* in_sizes, int n_in,
                              void* d_out, int out_size)
{
    const float* pre = (const float*)d_in[0];
    const float* f   = (const float*)d_in[1];
    float* out = (float*)d_out;

    float *w_ptr, *fq_ptr;
    cudaGetSymbolAddress((void**)&w_ptr,  g_w);
    cudaGetSymbolAddress((void**)&fq_ptr, g_fq);

    // iteration 1 + pack fq
    {
        dim3 blk(256, 1, 1);
        dim3 grd(N / 256, N, BSZ);
        jacobi_first<<<grd, blk>>>(pre, f, w_ptr, fq_ptr);
    }

    // 7 fused passes x 7 steps = iterations 2..50 (single launch per pass)
    {
        dim3 blk(32, TPY, 1);
        dim3 grd(NBX, NBY, BSZ);   // 19 x 64 x 16

        const float* s = w_ptr;
        for (int p = 0; p < 7; ++p) {
            float* d = (p & 1) ? w_ptr : out;   // final pass (p=6) -> out
            jacobi_fused<<<grd, blk>>>(s, fq_ptr, d);
            s = d;
        }
    }
}